// round 4
// baseline (speedup 1.0000x reference)
#include <cuda_runtime.h>

#define SPATIAL  3136            // 56*56
#define NBW      128             // T*B*heads*2 windows
#define SCALE2   0.35355339059327373f   // 2/sqrt(32)

// phase1 stage: 8-row chunk = 224 positions = 112 pairs, 56 16B-lines per channel
#define P1_ROWB   896                  // 56 lines * 16B
#define P1_TENSOR (32 * P1_ROWB)       // 28672 B
#define P1_BUF    (2 * P1_TENSOR)      // 57344 B (K+V for one chunk)
#define P1_SMEM   (2 * P1_BUF)         // 114688 B (double buffer)
#define P1_LINES  1792                 // 32 ch * 56 lines per tensor

__device__ float g_Pp[NBW * 2 * 1024];   // unscaled partial K^T V (2 slices)

typedef unsigned long long ull;

__device__ __forceinline__ void fma2(ull& d, ull a, ull b) {
    asm("fma.rn.f32x2 %0, %1, %2, %0;" : "+l"(d) : "l"(a), "l"(b));
}
__device__ __forceinline__ ull rep2(float x) {
    ull r; asm("mov.b64 %0, {%1, %1};" : "=l"(r) : "f"(x)); return r;
}
__device__ __forceinline__ float lo32(ull x) { return __uint_as_float((unsigned)x); }
__device__ __forceinline__ float hi32(ull x) { return __uint_as_float((unsigned)(x >> 32)); }

__device__ __forceinline__ void cp16(unsigned dst, const void* src) {
    asm volatile("cp.async.cg.shared.global [%0], [%1], 16;" :: "r"(dst), "l"(src));
}

// ---------------------------------------------------------------------------
// Phase 1: partial P = K^T V.  grid (128 bw, 2 slices), 256 threads.
// Slice 0 = chunks 0..3, slice 1 = chunks 4..6 (8-row chunks).
// Thread tile: 8 c1 x 4 c2, f32x2 over position pairs, posg = warp id.
// 2 blocks/SM co-resident (114KB smem, <=128 regs).
// ---------------------------------------------------------------------------
__global__ __launch_bounds__(256, 2)
void phase1(const float* __restrict__ K, const float* __restrict__ V) {
    extern __shared__ __align__(16) char sm[];
    const unsigned sm32 = (unsigned)__cvta_generic_to_shared(sm);

    const int tid  = threadIdx.x;
    const int bw   = blockIdx.x;
    const int sl   = blockIdx.y;
    const int cs0  = sl ? 4 : 0;
    const int nch  = sl ? 3 : 4;

    const int win  = bw & 1;
    const int head = (bw >> 1) & 7;
    const int tb   = bw >> 4;
    const int base = (tb * 256 + head * 32) * SPATIAL + win * 28;

    const int ti  = tid & 3;          // c1 group (8 channels)
    const int tj  = (tid >> 2) & 7;   // c2 group (4 channels)
    const int wid = tid >> 5;         // pos-pair group (warp)

    // staging: 14 cp.asyncs per thread per chunk, swizzle key = (c>>2)&7
    auto stage = [&](int ch, int buf) {
        const unsigned bufb = sm32 + buf * P1_BUF;
        const int gofs = base + ch * 448;             // 8 rows * 56
        #pragma unroll
        for (int it = 0; it < 14; it++) {
            int idx = it * 256 + tid;                 // 0..3583
            int tensor = (idx >= P1_LINES) ? 1 : 0;
            int rem = idx - tensor * P1_LINES;        // 0..1791
            int c = rem / 56;
            int g = rem - c * 56;
            int r = g / 7;
            int w4 = g - r * 7;
            const float* src = (tensor ? V : K) + gofs + c * SPATIAL + r * 56 + w4 * 4;
            int chs = g ^ ((c >> 2) & 7);
            unsigned dst = bufb + tensor * P1_TENSOR + c * P1_ROWB + chs * 16;
            cp16(dst, src);
        }
        asm volatile("cp.async.commit_group;");
    };

    ull acc[8][4];
    #pragma unroll
    for (int i = 0; i < 8; i++)
        #pragma unroll
        for (int j = 0; j < 4; j++) acc[i][j] = 0ull;

    stage(cs0, 0);

    for (int i = 0; i < nch; i++) {
        if (i < nch - 1) {
            stage(cs0 + i + 1, (i + 1) & 1);
            asm volatile("cp.async.wait_group 1;");
        } else {
            asm volatile("cp.async.wait_group 0;");
        }
        __syncthreads();

        const char* kB = sm + (i & 1) * P1_BUF;
        const char* vB = kB + P1_TENSOR;

        #pragma unroll
        for (int u = 0; u < 14; u++) {
            const int pr  = wid + u * 8;              // pair index 0..111
            const int col = pr >> 1;
            const unsigned sub = (pr & 1) << 3;
            ull kk[8], vv[4];
            #pragma unroll
            for (int i2 = 0; i2 < 8; i2++) {
                const int c = ti * 8 + i2;
                kk[i2] = *(const ull*)(kB + c * P1_ROWB
                        + ((unsigned)(col ^ ((c >> 2) & 7)) << 4) + sub);
            }
            #pragma unroll
            for (int j = 0; j < 4; j++) {
                const int c = tj * 4 + j;
                vv[j] = *(const ull*)(vB + c * P1_ROWB
                        + ((unsigned)(col ^ tj) << 4) + sub);
            }
            #pragma unroll
            for (int i2 = 0; i2 < 8; i2++)
                #pragma unroll
                for (int j = 0; j < 4; j++)
                    fma2(acc[i2][j], kk[i2], vv[j]);
        }
        __syncthreads();
    }

    // reduce over the 8 pos-warps via smem (buffers free now; need 32KB)
    float* red = (float*)sm;
    #pragma unroll
    for (int i2 = 0; i2 < 8; i2++)
        #pragma unroll
        for (int j = 0; j < 4; j++)
            red[wid * 1024 + (ti * 8 + i2) * 32 + tj * 4 + j] =
                lo32(acc[i2][j]) + hi32(acc[i2][j]);
    __syncthreads();

    float* gp = g_Pp + (bw * 2 + sl) * 1024;
    #pragma unroll
    for (int t = 0; t < 4; t++) {
        const int o = tid + t * 256;
        float s = red[o];
        #pragma unroll
        for (int w = 1; w < 8; w++) s += red[w * 1024 + o];
        gp[o] = s;
    }
}

// ---------------------------------------------------------------------------
// Phase 2: out = Q * P.  grid (128 bw, 7 chunks of 8 rows), 224 threads.
// Thread tile: 8 positions x 4 c2 channels. All lanes active.
// ---------------------------------------------------------------------------
__global__ __launch_bounds__(224, 4)
void phase2(const float* __restrict__ Q, float* __restrict__ O) {
    __shared__ __align__(16) float qs[32 * 224];
    __shared__ __align__(16) float ps[1024];

    const int tid = threadIdx.x;
    const int bw  = blockIdx.x;
    const int ck  = blockIdx.y;
    const int win  = bw & 1;
    const int head = (bw >> 1) & 7;
    const int tb   = bw >> 4;
    const int base = (tb * 256 + head * 32) * SPATIAL + win * 28 + ck * 448;

    // P = (partial0 + partial1) * scale
    const float* p0 = g_Pp + bw * 2048;
    for (int o = tid; o < 1024; o += 224)
        ps[o] = (p0[o] + p0[1024 + o]) * SCALE2;

    // stage Q tile: 32 channels x 224 positions = 1792 float4 lines
    #pragma unroll
    for (int it = 0; it < 8; it++) {
        int idx = it * 224 + tid;           // 0..1791
        int c = idx / 56;
        int g = idx - c * 56;
        int r = g / 7;
        int w4 = g - r * 7;
        *(float4*)&qs[c * 224 + g * 4] =
            *(const float4*)(Q + base + c * SPATIAL + r * 56 + w4 * 4);
    }
    __syncthreads();

    const int c2g  = tid & 7;               // 4 c2 each
    const int posg = tid >> 3;               // 0..27
    const int pbase = posg * 8;

    ull a[4][4];
    #pragma unroll
    for (int p = 0; p < 4; p++)
        #pragma unroll
        for (int j = 0; j < 4; j++) a[p][j] = 0ull;

    #pragma unroll
    for (int c1 = 0; c1 < 32; c1++) {
        ulonglong2 qa = *(const ulonglong2*)&qs[c1 * 224 + pbase];
        ulonglong2 qb = *(const ulonglong2*)&qs[c1 * 224 + pbase + 4];
        float4 p4 = *(const float4*)&ps[c1 * 32 + c2g * 4];
        const float pv[4] = {p4.x, p4.y, p4.z, p4.w};
        #pragma unroll
        for (int j = 0; j < 4; j++) {
            ull pj = rep2(pv[j]);
            fma2(a[0][j], qa.x, pj);
            fma2(a[1][j], qa.y, pj);
            fma2(a[2][j], qb.x, pj);
            fma2(a[3][j], qb.y, pj);
        }
    }

    #pragma unroll
    for (int j = 0; j < 4; j++) {
        const int c2 = c2g * 4 + j;
        #pragma unroll
        for (int h = 0; h < 2; h++) {
            const int p  = pbase + h * 4;
            const int rr = p / 28;
            const int ww = p - rr * 28;
            float4 o4;
            o4.x = lo32(a[2 * h][j]);
            o4.y = hi32(a[2 * h][j]);
            o4.z = lo32(a[2 * h + 1][j]);
            o4.w = hi32(a[2 * h + 1][j]);
            *(float4*)(O + base + c2 * SPATIAL + rr * 56 + ww) = o4;
        }
    }
}

// ---------------------------------------------------------------------------
extern "C" void kernel_launch(void* const* d_in, const int* in_sizes, int n_in,
                              void* d_out, int out_size) {
    const float* q = (const float*)d_in[0];
    const float* k = (const float*)d_in[1];
    const float* v = (const float*)d_in[2];
    float* out = (float*)d_out;

    cudaFuncSetAttribute(phase1, cudaFuncAttributeMaxDynamicSharedMemorySize, P1_SMEM);

    phase1<<<dim3(NBW, 2), 256, P1_SMEM>>>(k, v);
    phase2<<<dim3(NBW, 7), 224>>>(q, out);
}

// round 5
// speedup vs baseline: 1.1104x; 1.1104x over previous
#include <cuda_runtime.h>

#define SPATIAL  3136            // 56*56
#define NBW      128             // T*B*heads*2 windows
#define SCALE2   0.35355339059327373f   // 2/sqrt(32)

// phase1: 4-row chunks = 112 positions = 56 pairs, 28 16B-lines per channel
#define P1_ROWB   512                  // 32 line slots * 16B (28 used, swizzle room)
#define P1_TENSOR (32 * P1_ROWB)       // 16384 B
#define P1_BUF    (2 * P1_TENSOR)      // 32768 B (K+V one chunk)
#define P1_NBUF   3
#define P1_SMEM   (P1_NBUF * P1_BUF)   // 98304 B
#define P1_LPT    896                  // lines per tensor per chunk (32ch * 28)

__device__ float g_Pp[NBW * 2 * 1024];   // unscaled partial K^T V (2 slices)

typedef unsigned long long ull;

__device__ __forceinline__ void fma2(ull& d, ull a, ull b) {
    asm("fma.rn.f32x2 %0, %1, %2, %0;" : "+l"(d) : "l"(a), "l"(b));
}
__device__ __forceinline__ ull rep2(float x) {
    ull r; asm("mov.b64 %0, {%1, %1};" : "=l"(r) : "f"(x)); return r;
}
__device__ __forceinline__ float lo32(ull x) { return __uint_as_float((unsigned)x); }
__device__ __forceinline__ float hi32(ull x) { return __uint_as_float((unsigned)(x >> 32)); }

__device__ __forceinline__ void cp16(unsigned dst, const void* src) {
    asm volatile("cp.async.cg.shared.global [%0], [%1], 16;" :: "r"(dst), "l"(src));
}

// ---------------------------------------------------------------------------
// Phase 1: partial P = K^T V.  grid (128 bw, 2 slices of 7 chunks), 256 thr.
// 4-row chunks, triple-buffered cp.async ring, 2 blocks/SM.
// Thread tile: 8 c1 x 4 c2, f32x2 over position pairs (warp = pair group).
// ---------------------------------------------------------------------------
__global__ __launch_bounds__(256, 2)
void phase1(const float* __restrict__ K, const float* __restrict__ V) {
    extern __shared__ __align__(16) char sm[];
    const unsigned sm32 = (unsigned)__cvta_generic_to_shared(sm);

    const int tid  = threadIdx.x;
    const int bw   = blockIdx.x;
    const int sl   = blockIdx.y;
    const int c0   = sl * 7;            // 7 chunks per slice, balanced

    const int win  = bw & 1;
    const int head = (bw >> 1) & 7;
    const int tb   = bw >> 4;
    const int base = (tb * 256 + head * 32) * SPATIAL + win * 28;

    const int ti  = tid & 3;            // c1 group (8 channels)
    const int tj  = (tid >> 2) & 7;     // c2 group (4 channels)
    const int wid = tid >> 5;           // position-pair group (warp)
    const int keyA = ti * 2;            // swizzle key for kk[0..3]
    const int keyB = ti * 2 + 1;        // swizzle key for kk[4..7]

    // staging: 7 cp.asyncs per thread per chunk, key = (c>>2)&7
    auto stage = [&](int ch, int buf) {
        const unsigned bufb = sm32 + buf * P1_BUF;
        const int gofs = base + ch * 224;           // 4 rows * 56
        #pragma unroll
        for (int it = 0; it < 7; it++) {
            int idx = it * 256 + tid;               // 0..1791
            int tensor = (idx >= P1_LPT) ? 1 : 0;
            int rem = idx - tensor * P1_LPT;        // 0..895
            int c = rem / 28;
            int g = rem - c * 28;                   // line 0..27
            int r = g / 7;
            int w4 = g - r * 7;
            const float* src = (tensor ? V : K) + gofs + c * SPATIAL + r * 56 + w4 * 4;
            int chs = g ^ ((c >> 2) & 7);           // 0..31, fits slot row
            unsigned dst = bufb + tensor * P1_TENSOR + c * P1_ROWB + chs * 16;
            cp16(dst, src);
        }
        asm volatile("cp.async.commit_group;");
    };

    ull acc[8][4];
    #pragma unroll
    for (int i = 0; i < 8; i++)
        #pragma unroll
        for (int j = 0; j < 4; j++) acc[i][j] = 0ull;

    stage(c0, 0);
    stage(c0 + 1, 1);

    #pragma unroll
    for (int i = 0; i < 7; i++) {
        if (i < 5) {
            stage(c0 + i + 2, (i + 2) % 3);
            asm volatile("cp.async.wait_group 2;");
        } else if (i == 5) {
            asm volatile("cp.async.wait_group 1;");
        } else {
            asm volatile("cp.async.wait_group 0;");
        }
        __syncthreads();

        const char* kB = sm + (i % 3) * P1_BUF;
        const char* vB = kB + P1_TENSOR;

        auto loadA = [&](int u, ull* ka) {          // kk[0..3]
            const int pr = wid + u * 8;
            const int col = pr >> 1;
            const unsigned off = ((unsigned)(col ^ keyA) << 4) + ((pr & 1) << 3);
            #pragma unroll
            for (int i2 = 0; i2 < 4; i2++)
                ka[i2] = *(const ull*)(kB + (ti * 8 + i2) * P1_ROWB + off);
        };
        auto loadB = [&](int u, ull* kb) {          // kk[4..7]
            const int pr = wid + u * 8;
            const int col = pr >> 1;
            const unsigned off = ((unsigned)(col ^ keyB) << 4) + ((pr & 1) << 3);
            #pragma unroll
            for (int i2 = 0; i2 < 4; i2++)
                kb[i2] = *(const ull*)(kB + (ti * 8 + 4 + i2) * P1_ROWB + off);
        };
        auto loadV = [&](int u, ull* v) {
            const int pr = wid + u * 8;
            const int col = pr >> 1;
            const unsigned off = ((unsigned)(col ^ tj) << 4) + ((pr & 1) << 3);
            #pragma unroll
            for (int j = 0; j < 4; j++)
                v[j] = *(const ull*)(vB + (tj * 4 + j) * P1_ROWB + off);
        };

        ull kkA[4], kkB[4], vv[4], kkA2[4], vv2[4];
        loadA(0, kkA);
        loadV(0, vv);
        #pragma unroll
        for (int u = 0; u < 7; u++) {
            loadB(u, kkB);
            if (u < 6) { loadA(u + 1, kkA2); loadV(u + 1, vv2); }
            #pragma unroll
            for (int i2 = 0; i2 < 4; i2++)
                #pragma unroll
                for (int j = 0; j < 4; j++)
                    fma2(acc[i2][j], kkA[i2], vv[j]);
            #pragma unroll
            for (int i2 = 0; i2 < 4; i2++)
                #pragma unroll
                for (int j = 0; j < 4; j++)
                    fma2(acc[4 + i2][j], kkB[i2], vv[j]);
            if (u < 6) {
                #pragma unroll
                for (int t = 0; t < 4; t++) { kkA[t] = kkA2[t]; vv[t] = vv2[t]; }
            }
        }
        __syncthreads();
    }

    // reduce 8 pos-warps via smem (buffers free now)
    float* red = (float*)sm;
    #pragma unroll
    for (int i2 = 0; i2 < 8; i2++)
        #pragma unroll
        for (int j = 0; j < 4; j++)
            red[wid * 1024 + (ti * 8 + i2) * 32 + tj * 4 + j] =
                lo32(acc[i2][j]) + hi32(acc[i2][j]);
    __syncthreads();

    float* gp = g_Pp + (bw * 2 + sl) * 1024;
    #pragma unroll
    for (int t = 0; t < 4; t++) {
        const int o = tid + t * 256;
        float s = red[o];
        #pragma unroll
        for (int w = 1; w < 8; w++) s += red[w * 1024 + o];
        gp[o] = s;
    }
}

// ---------------------------------------------------------------------------
// Phase 2: out = Q * P.  grid (128 bw, 7 chunks of 8 rows), 128 threads.
// Thread tile: 8 positions x 8 c2; software-pipelined c1 loop.
// ---------------------------------------------------------------------------
__global__ __launch_bounds__(128)
void phase2(const float* __restrict__ Q, float* __restrict__ O) {
    __shared__ __align__(16) float qs[32 * 224];
    __shared__ __align__(16) float ps[1024];

    const int tid = threadIdx.x;
    const int bw  = blockIdx.x;
    const int ck  = blockIdx.y;
    const int win  = bw & 1;
    const int head = (bw >> 1) & 7;
    const int tb   = bw >> 4;
    const int base = (tb * 256 + head * 32) * SPATIAL + win * 28 + ck * 448;

    // P = (partial0 + partial1) * scale  (vectorized)
    const float* p0 = g_Pp + bw * 2048;
    #pragma unroll
    for (int t = 0; t < 2; t++) {
        const int i4 = (tid + t * 128) * 4;
        float4 a = *(const float4*)(p0 + i4);
        float4 b = *(const float4*)(p0 + 1024 + i4);
        float4 s;
        s.x = (a.x + b.x) * SCALE2;
        s.y = (a.y + b.y) * SCALE2;
        s.z = (a.z + b.z) * SCALE2;
        s.w = (a.w + b.w) * SCALE2;
        *(float4*)&ps[i4] = s;
    }

    // stage Q tile via cp.async: 1792 lines / 128 thr = 14 each
    const unsigned qsa = (unsigned)__cvta_generic_to_shared(qs);
    #pragma unroll
    for (int it = 0; it < 14; it++) {
        int idx = it * 128 + tid;
        int c = idx / 56;
        int g = idx - c * 56;
        int r = g / 7;
        int w4 = g - r * 7;
        cp16(qsa + (c * 224 + g * 4) * 4,
             Q + base + c * SPATIAL + r * 56 + w4 * 4);
    }
    asm volatile("cp.async.commit_group;");
    asm volatile("cp.async.wait_group 0;");
    __syncthreads();

    const int c2g  = tid & 3;               // 8 c2 each
    const int posg = tid >> 2;               // 0..31, active < 28
    if (posg >= 28) return;
    const int pbase = posg * 8;

    ull a[4][8];
    #pragma unroll
    for (int p = 0; p < 4; p++)
        #pragma unroll
        for (int j = 0; j < 8; j++) a[p][j] = 0ull;

    ulonglong2 qa = *(const ulonglong2*)&qs[pbase];
    ulonglong2 qb = *(const ulonglong2*)&qs[pbase + 4];
    float4 pa = *(const float4*)&ps[c2g * 8];
    float4 pb = *(const float4*)&ps[c2g * 8 + 4];

    #pragma unroll
    for (int c1 = 0; c1 < 32; c1++) {
        ulonglong2 qa2, qb2;
        float4 pa2, pb2;
        if (c1 < 31) {
            qa2 = *(const ulonglong2*)&qs[(c1 + 1) * 224 + pbase];
            qb2 = *(const ulonglong2*)&qs[(c1 + 1) * 224 + pbase + 4];
            pa2 = *(const float4*)&ps[(c1 + 1) * 32 + c2g * 8];
            pb2 = *(const float4*)&ps[(c1 + 1) * 32 + c2g * 8 + 4];
        }
        const float pv[8] = {pa.x, pa.y, pa.z, pa.w, pb.x, pb.y, pb.z, pb.w};
        #pragma unroll
        for (int j = 0; j < 8; j++) {
            ull pj = rep2(pv[j]);
            fma2(a[0][j], qa.x, pj);
            fma2(a[1][j], qa.y, pj);
            fma2(a[2][j], qb.x, pj);
            fma2(a[3][j], qb.y, pj);
        }
        if (c1 < 31) { qa = qa2; qb = qb2; pa = pa2; pb = pb2; }
    }

    #pragma unroll
    for (int j = 0; j < 8; j++) {
        const int c2 = c2g * 8 + j;
        #pragma unroll
        for (int h = 0; h < 2; h++) {
            const int p  = pbase + h * 4;
            const int rr = p / 28;
            const int ww = p - rr * 28;
            float4 o4;
            o4.x = lo32(a[2 * h][j]);
            o4.y = hi32(a[2 * h][j]);
            o4.z = lo32(a[2 * h + 1][j]);
            o4.w = hi32(a[2 * h + 1][j]);
            *(float4*)(O + base + c2 * SPATIAL + rr * 56 + ww) = o4;
        }
    }
}

// ---------------------------------------------------------------------------
extern "C" void kernel_launch(void* const* d_in, const int* in_sizes, int n_in,
                              void* d_out, int out_size) {
    const float* q = (const float*)d_in[0];
    const float* k = (const float*)d_in[1];
    const float* v = (const float*)d_in[2];
    float* out = (float*)d_out;

    cudaFuncSetAttribute(phase1, cudaFuncAttributeMaxDynamicSharedMemorySize, P1_SMEM);

    phase1<<<dim3(NBW, 2), 256, P1_SMEM>>>(k, v);
    phase2<<<dim3(NBW, 7), 128>>>(q, out);
}